// round 11
// baseline (speedup 1.0000x reference)
#include <cuda_runtime.h>
#include <cstdint>

#define T_  256
#define B_  128
#define I_  512
#define H_  1024
#define L_  4
#define G3H 3072
#define TB  (T_ * B_)

// scan tiling
#define RT 64            // batch rows per CTA
#define CT 16            // cols per gate per CTA (48 W rows total)
// fragment-packed h: row-block (16 rows) x 1024 k = 16384 words
#define RBW 16384
// per-chunk staging: 4 row-blocks x 8 ko x 128 words = 4096 words
#define CHUNK_WORDS 4096
#define WS_WORDS (48 * 1024)          // 49152 words, fragment-packed W
#define SCAN_SMEM_WORDS (WS_WORDS + 2 * CHUNK_WORDS)
#define SCAN_SMEM_BYTES (SCAN_SMEM_WORDS * 4)   // 229376 <= 232448
#define RING 4

// Scratch
__device__ float    g_gi[(size_t)TB * G3H];   // per-layer input projections
__device__ float    g_ys[(size_t)TB * H_];    // inter-layer activations
__device__ uint32_t g_htf[RING][B_ * H_];     // h ring, TF32 bits, FRAGMENT-PACKED
__device__ unsigned g_cnt[2][16];             // per (batch-tile, k-chunk) ready counters
__device__ unsigned g_ack;                    // end-of-scan reset ack

__device__ __forceinline__ uint32_t f2tf(float x) {
    uint32_t r;
    asm("cvt.rna.tf32.f32 %0, %1;\n" : "=r"(r) : "f"(x));
    return r;
}

__device__ __forceinline__ void mma8(float* c, const uint32_t* a, const uint32_t* b) {
    asm volatile(
        "mma.sync.aligned.m16n8k8.row.col.f32.tf32.tf32.f32 "
        "{%0,%1,%2,%3}, {%4,%5,%6,%7}, {%8,%9}, {%0,%1,%2,%3};\n"
        : "+f"(c[0]), "+f"(c[1]), "+f"(c[2]), "+f"(c[3])
        : "r"(a[0]), "r"(a[1]), "r"(a[2]), "r"(a[3]), "r"(b[0]), "r"(b[1]));
}

__device__ __forceinline__ void cp16cg(uint32_t dst_smem, const void* src) {
    asm volatile("cp.async.cg.shared.global [%0], [%1], 16;\n"
                 :: "r"(dst_smem), "l"(src));
}

__device__ __forceinline__ void waitcnt(const unsigned* p, unsigned thr) {
    unsigned v;
    do {
        asm volatile("ld.global.acquire.gpu.u32 %0, [%1];"
                     : "=r"(v) : "l"(p) : "memory");
    } while (v < thr);
}

// packed address of h element (m, k)
__device__ __forceinline__ int hpack(int m, int k) {
    return (m >> 4) * RBW + (k >> 3) * 128 +
           ((m & 7) * 4 + (k & 3)) * 4 + ((m >> 3) & 1) + 2 * ((k >> 2) & 1);
}

// ---------------------------------------------------------------------------
// gi = A @ W^T + bias      (unchanged)
// ---------------------------------------------------------------------------
__global__ __launch_bounds__(256) void gi_gemm(
    const float* __restrict__ A_ext,
    const float* __restrict__ W,
    const float* __restrict__ bias,
    int K)
{
    __shared__ uint32_t As[128][36];
    __shared__ uint32_t Bs[64][36];

    const float* A = A_ext ? A_ext : g_ys;

    int n0 = blockIdx.x * 64;
    int m0 = blockIdx.y * 128;
    int tid = threadIdx.x;
    int warp = tid >> 5, lane = tid & 31;
    int g4 = lane >> 2, tig = lane & 3;
    int wm = warp & 3, wn = warp >> 2;
    int mb = wm * 32, nb = wn * 32;

    float acc[2][4][4];
    #pragma unroll
    for (int i = 0; i < 2; i++)
        #pragma unroll
        for (int j = 0; j < 4; j++)
            #pragma unroll
            for (int k = 0; k < 4; k++) acc[i][j][k] = 0.f;

    int arow = tid >> 3;
    int acol = (tid & 7) * 4;

    for (int k0 = 0; k0 < K; k0 += 32) {
        #pragma unroll
        for (int r = 0; r < 4; r++) {
            int row = arow + r * 32;
            float4 v = *reinterpret_cast<const float4*>(A + (size_t)(m0 + row) * K + k0 + acol);
            As[row][acol]     = f2tf(v.x);
            As[row][acol + 1] = f2tf(v.y);
            As[row][acol + 2] = f2tf(v.z);
            As[row][acol + 3] = f2tf(v.w);
        }
        #pragma unroll
        for (int r = 0; r < 2; r++) {
            int row = arow + r * 32;
            float4 v = *reinterpret_cast<const float4*>(W + (size_t)(n0 + row) * K + k0 + acol);
            Bs[row][acol]     = f2tf(v.x);
            Bs[row][acol + 1] = f2tf(v.y);
            Bs[row][acol + 2] = f2tf(v.z);
            Bs[row][acol + 3] = f2tf(v.w);
        }
        __syncthreads();

        #pragma unroll
        for (int kk = 0; kk < 32; kk += 8) {
            uint32_t af[2][4], bf[4][2];
            #pragma unroll
            for (int mf = 0; mf < 2; mf++) {
                int r0 = mb + mf * 16 + g4;
                af[mf][0] = As[r0][kk + tig];
                af[mf][1] = As[r0 + 8][kk + tig];
                af[mf][2] = As[r0][kk + tig + 4];
                af[mf][3] = As[r0 + 8][kk + tig + 4];
            }
            #pragma unroll
            for (int nf = 0; nf < 4; nf++) {
                int c0 = nb + nf * 8 + g4;
                bf[nf][0] = Bs[c0][kk + tig];
                bf[nf][1] = Bs[c0][kk + tig + 4];
            }
            #pragma unroll
            for (int mf = 0; mf < 2; mf++)
                #pragma unroll
                for (int nf = 0; nf < 4; nf++)
                    mma8(acc[mf][nf], af[mf], bf[nf]);
        }
        __syncthreads();
    }

    #pragma unroll
    for (int mf = 0; mf < 2; mf++) {
        #pragma unroll
        for (int nf = 0; nf < 4; nf++) {
            int col = n0 + nb + nf * 8 + tig * 2;
            float b0 = bias[col], b1 = bias[col + 1];
            int r0 = m0 + mb + mf * 16 + g4;
            g_gi[(size_t)r0 * G3H + col]           = acc[mf][nf][0] + b0;
            g_gi[(size_t)r0 * G3H + col + 1]       = acc[mf][nf][1] + b1;
            g_gi[(size_t)(r0 + 8) * G3H + col]     = acc[mf][nf][2] + b0;
            g_gi[(size_t)(r0 + 8) * G3H + col + 1] = acc[mf][nf][3] + b1;
        }
    }
}

// ---------------------------------------------------------------------------
// Persistent scan, fragment-packed layouts, BARRIER-FREE dataflow pacing.
// Grid = 128 CTAs (2 batch tiles x 64 col groups), 256 threads.
// h lives in a depth-4 ring; chunk c of step t+1 is gated on a per-chunk
// counter bumped by its 4 producer CTAs (cg = 4c..4c+3) at step-t epilogue.
// No grid-wide barrier anywhere.
// ---------------------------------------------------------------------------
__global__ __launch_bounds__(256, 1) void gru_scan(
    const float* __restrict__ Whh,
    const float* __restrict__ bhh,
    const int*   __restrict__ lens,
    const float* __restrict__ h0,
    float* __restrict__ y_last,
    float* __restrict__ h_final)
{
    extern __shared__ uint32_t sm[];
    uint32_t* Ws = sm;                     // WS_WORDS, fragment-packed
    uint32_t* Ab = sm + WS_WORDS;          // 2 x CHUNK_WORDS

    int cta = blockIdx.x;
    int bt = cta & 1;
    int cg = cta >> 1;
    int tid = threadIdx.x;
    int lane = tid & 31;
    int warp = tid >> 5;
    int g4 = lane >> 2, tig = lane & 3;
    int wrow = warp & 3, wcol = warp >> 2;

    uint32_t ab_u32 = (uint32_t)__cvta_generic_to_shared(Ab);

    // Pack W slice into smem fragment order
    for (int i = tid; i < 48 * 256; i += 256) {
        int r = i >> 8;                  // packed W row 0..47
        int c4 = i & 255;                // float4 index along K
        int q = r >> 4;
        int rl = r & 15;
        int wc = rl >> 3, g4r = rl & 7;
        float4 v = *reinterpret_cast<const float4*>(
            Whh + (size_t)(q * H_ + cg * CT + rl) * H_ + c4 * 4);
        int ko = c4 >> 1;
        int hi = c4 & 1;
        uint32_t* base = Ws + ((size_t)(q * 2 + wc) * 128 + ko) * 64 + g4r * 8 + hi;
        base[0] = f2tf(v.x);
        base[2] = f2tf(v.y);
        base[4] = f2tf(v.z);
        base[6] = f2tf(v.w);
    }

    // Per-thread constants + register-resident h
    int m0 = bt * RT + wrow * 16 + g4;
    int jbase = cg * CT + wcol * 8 + tig * 2;
    float bj[3][2];
    #pragma unroll
    for (int q = 0; q < 3; q++) {
        bj[q][0] = bhh[q * H_ + jbase];
        bj[q][1] = bhh[q * H_ + jbase + 1];
    }
    int len0 = lens[m0];
    int len1 = lens[m0 + 8];

    float hreg[2][2];
    #pragma unroll
    for (int ri = 0; ri < 2; ri++) {
        int m = m0 + ri * 8;
        #pragma unroll
        for (int ci = 0; ci < 2; ci++) {
            hreg[ri][ci] = h0[(size_t)m * H_ + jbase + ci];
            g_htf[0][hpack(m, jbase + ci)] = f2tf(hreg[ri][ci]);
        }
    }

    // publish h0 portion: counter bump stands in for the old global barrier
    __threadfence();
    __syncthreads();
    if (tid == 0) atomicAdd(&g_cnt[bt][cg >> 2], 1u);

    for (int t = 0; t < T_; t++) {
        const uint32_t* hin = g_htf[t & (RING - 1)];
        uint32_t* hout = g_htf[(t + 1) & (RING - 1)];
        unsigned thr = 4u * (unsigned)(t + 1);   // producers per chunk = 4

        // gate chunk 0, then prefetch it
        if (tid == 0) waitcnt(&g_cnt[bt][0], thr);
        __syncthreads();
        {
            #pragma unroll
            for (int it = 0; it < 4; it++) {
                cp16cg(ab_u32 + (uint32_t)(it * 1024 + tid * 4) * 4,
                       hin + (size_t)(bt * 4 + it) * RBW + tid * 4);
            }
            asm volatile("cp.async.commit_group;\n" ::: "memory");
        }

        // prefetch gi for this step
        float gir[2][3][2];
        {
            const float* gi_t = g_gi + (size_t)t * B_ * G3H;
            #pragma unroll
            for (int ri = 0; ri < 2; ri++) {
                const float* gi = gi_t + (size_t)(m0 + ri * 8) * G3H;
                #pragma unroll
                for (int q = 0; q < 3; q++) {
                    gir[ri][q][0] = gi[q * H_ + jbase];
                    gir[ri][q][1] = gi[q * H_ + jbase + 1];
                }
            }
        }

        float acc[3][4];
        #pragma unroll
        for (int q = 0; q < 3; q++)
            #pragma unroll
            for (int i = 0; i < 4; i++) acc[q][i] = 0.f;

        for (int c = 0; c < 16; c++) {
            asm volatile("cp.async.wait_group 0;\n" ::: "memory");
            if (tid == 0 && c + 1 < 16) waitcnt(&g_cnt[bt][c + 1], thr);
            __syncthreads();
            if (c + 1 < 16) {
                uint32_t dstb = ab_u32 + (uint32_t)(((c + 1) & 1) * CHUNK_WORDS) * 4;
                #pragma unroll
                for (int it = 0; it < 4; it++) {
                    cp16cg(dstb + (uint32_t)(it * 1024 + tid * 4) * 4,
                           hin + (size_t)(bt * 4 + it) * RBW + (c + 1) * 1024 + tid * 4);
                }
                asm volatile("cp.async.commit_group;\n" ::: "memory");
            }

            const uint32_t* As = Ab + (c & 1) * CHUNK_WORDS + wrow * 1024 + lane * 4;
            #pragma unroll
            for (int kk8 = 0; kk8 < 8; kk8++) {
                uint4 af = *reinterpret_cast<const uint4*>(As + kk8 * 128);
                #pragma unroll
                for (int q = 0; q < 3; q++) {
                    uint2 bf = *reinterpret_cast<const uint2*>(
                        Ws + ((size_t)(q * 2 + wcol) * 128 + c * 8 + kk8) * 64 + lane * 2);
                    mma8(acc[q], reinterpret_cast<const uint32_t*>(&af),
                                 reinterpret_cast<const uint32_t*>(&bf));
                }
            }
        }

        // Gate epilogue: compute + write packed h to ring buffer
        float ynew[2][2];
        #pragma unroll
        for (int ri = 0; ri < 2; ri++) {
            int m = m0 + ri * 8;
            bool msk = t < (ri ? len1 : len0);
            #pragma unroll
            for (int ci = 0; ci < 2; ci++) {
                int ai = ri * 2 + ci;
                float ghr = acc[0][ai] + bj[0][ci];
                float ghz = acc[1][ai] + bj[1][ci];
                float ghn = acc[2][ai] + bj[2][ci];
                float rg = 1.f / (1.f + __expf(-(gir[ri][0][ci] + ghr)));
                float zg = 1.f / (1.f + __expf(-(gir[ri][1][ci] + ghz)));
                float ng = tanhf(gir[ri][2][ci] + rg * ghn);
                float hnew = (1.f - zg) * ng + zg * hreg[ri][ci];
                float hv = msk ? hnew : hreg[ri][ci];
                hreg[ri][ci] = hv;
                ynew[ri][ci] = msk ? hnew : 0.f;
                hout[hpack(m, jbase + ci)] = f2tf(hv);
            }
        }

        // publish this CTA's h chunk contribution for step t+1
        __threadfence();
        __syncthreads();
        if (tid == 0) atomicAdd(&g_cnt[bt][cg >> 2], 1u);

        // y / h_final stores off the critical path
        float* yrow = y_last ? (y_last + (size_t)t * B_ * H_)
                             : (g_ys + (size_t)t * B_ * H_);
        #pragma unroll
        for (int ri = 0; ri < 2; ri++) {
            int m = m0 + ri * 8;
            yrow[(size_t)m * H_ + jbase]     = ynew[ri][0];
            yrow[(size_t)m * H_ + jbase + 1] = ynew[ri][1];
            if (t == T_ - 1) {
                h_final[(size_t)m * H_ + jbase]     = hreg[ri][0];
                h_final[(size_t)m * H_ + jbase + 1] = hreg[ri][1];
            }
        }
    }

    // last CTA to finish resets counters for the next scan / next graph replay
    __syncthreads();
    if (tid == 0) {
        __threadfence();
        unsigned a = atomicAdd(&g_ack, 1u);
        if (a == 127u) {
            #pragma unroll
            for (int b = 0; b < 2; b++)
                #pragma unroll
                for (int c = 0; c < 16; c++) g_cnt[b][c] = 0u;
            g_ack = 0u;
            __threadfence();
        }
    }
}

extern "C" void kernel_launch(void* const* d_in, const int* in_sizes, int n_in,
                              void* d_out, int out_size) {
    const float* x          = (const float*)d_in[0];
    const float* hidden     = (const float*)d_in[1];
    const float* w_ih0      = (const float*)d_in[2];
    const float* w_ih_rest  = (const float*)d_in[3];
    const float* w_hh       = (const float*)d_in[4];
    const float* b_ih       = (const float*)d_in[5];
    const float* b_hh       = (const float*)d_in[6];
    const int*   lens       = (const int*)d_in[n_in - 1];

    float* out_ys = (float*)d_out;
    float* out_h  = out_ys + (size_t)T_ * B_ * H_;

    cudaFuncSetAttribute(gru_scan, cudaFuncAttributeMaxDynamicSharedMemorySize,
                         SCAN_SMEM_BYTES);

    for (int l = 0; l < L_; l++) {
        int K = (l == 0) ? I_ : H_;
        const float* wih = (l == 0) ? w_ih0 : (w_ih_rest + (size_t)(l - 1) * G3H * H_);
        dim3 grid(G3H / 64, TB / 128);
        gi_gemm<<<grid, 256>>>((l == 0) ? x : nullptr, wih, b_ih + (size_t)l * G3H, K);

        gru_scan<<<128, 256, SCAN_SMEM_BYTES>>>(
            w_hh + (size_t)l * G3H * H_,
            b_hh + (size_t)l * G3H,
            lens,
            hidden + (size_t)l * B_ * H_,
            (l == L_ - 1) ? out_ys : nullptr,
            out_h + (size_t)l * B_ * H_);
    }
}

// round 13
// speedup vs baseline: 1.1031x; 1.1031x over previous
#include <cuda_runtime.h>
#include <cstdint>

#define T_  256
#define B_  128
#define I_  512
#define H_  1024
#define L_  4
#define G3H 3072
#define TB  (T_ * B_)

#define NCTA 128
#define RBW 16384                 // 16-row block stride in g_htf (words)
#define CHUNK_WORDS 4096          // 64 rows x 64 k staged chunk
#define WS_WORDS (48 * 1024)      // fragment-packed W (words)
#define SCAN_SMEM_BYTES ((WS_WORDS + 2 * CHUNK_WORDS) * 4)   // 229376 <= 232448

// Scratch
__device__ float    g_gi[(size_t)TB * G3H];
__device__ float    g_ys[(size_t)TB * H_];
__device__ uint32_t g_htf[2][B_ * H_];   // h ping-pong, TF32 bits, fragment-packed
__device__ unsigned g_bar, g_ack;

__device__ __forceinline__ uint32_t f2tf(float x) {
    uint32_t r; asm("cvt.rna.tf32.f32 %0, %1;\n" : "=r"(r) : "f"(x)); return r;
}
__device__ __forceinline__ void mma8(float* c, const uint32_t* a, const uint32_t* b) {
    asm volatile("mma.sync.aligned.m16n8k8.row.col.f32.tf32.tf32.f32 "
        "{%0,%1,%2,%3}, {%4,%5,%6,%7}, {%8,%9}, {%0,%1,%2,%3};\n"
        : "+f"(c[0]), "+f"(c[1]), "+f"(c[2]), "+f"(c[3])
        : "r"(a[0]), "r"(a[1]), "r"(a[2]), "r"(a[3]), "r"(b[0]), "r"(b[1]));
}
__device__ __forceinline__ void cp16cg(uint32_t d, const void* s) {
    asm volatile("cp.async.cg.shared.global [%0], [%1], 16;\n" :: "r"(d), "l"(s));
}
// packed address of h element (m, k)  [identical to round 4 — proven]
__device__ __forceinline__ int hpack(int m, int k) {
    return (m >> 4) * RBW + (k >> 3) * 128 +
           ((m & 7) * 4 + (k & 3)) * 4 + ((m >> 3) & 1) + 2 * ((k >> 2) & 1);
}

// ---------------- gi = A @ Wih^T + b_ih (+ b_hh folded for r/z gates) -------
__global__ __launch_bounds__(256) void gi_gemm(
    const float* __restrict__ A_ext, const float* __restrict__ W,
    const float* __restrict__ bias, const float* __restrict__ bhh, int K)
{
    __shared__ uint32_t As[128][36];
    __shared__ uint32_t Bs[64][36];
    const float* A = A_ext ? A_ext : g_ys;
    int n0 = blockIdx.x * 64, m0 = blockIdx.y * 128;
    int tid = threadIdx.x, warp = tid >> 5, lane = tid & 31;
    int g4 = lane >> 2, tig = lane & 3;
    int mb = (warp & 3) * 32, nb = (warp >> 2) * 32;
    float acc[2][4][4];
    #pragma unroll
    for (int i = 0; i < 2; i++)
        #pragma unroll
        for (int j = 0; j < 4; j++)
            #pragma unroll
            for (int k = 0; k < 4; k++) acc[i][j][k] = 0.f;
    int arow = tid >> 3, acol = (tid & 7) * 4;
    for (int k0 = 0; k0 < K; k0 += 32) {
        #pragma unroll
        for (int r = 0; r < 4; r++) {
            int row = arow + r * 32;
            float4 v = *reinterpret_cast<const float4*>(A + (size_t)(m0 + row) * K + k0 + acol);
            As[row][acol] = f2tf(v.x); As[row][acol+1] = f2tf(v.y);
            As[row][acol+2] = f2tf(v.z); As[row][acol+3] = f2tf(v.w);
        }
        #pragma unroll
        for (int r = 0; r < 2; r++) {
            int row = arow + r * 32;
            float4 v = *reinterpret_cast<const float4*>(W + (size_t)(n0 + row) * K + k0 + acol);
            Bs[row][acol] = f2tf(v.x); Bs[row][acol+1] = f2tf(v.y);
            Bs[row][acol+2] = f2tf(v.z); Bs[row][acol+3] = f2tf(v.w);
        }
        __syncthreads();
        #pragma unroll
        for (int kk = 0; kk < 32; kk += 8) {
            uint32_t af[2][4], bf[4][2];
            #pragma unroll
            for (int mf = 0; mf < 2; mf++) {
                int r0 = mb + mf * 16 + g4;
                af[mf][0] = As[r0][kk+tig];   af[mf][1] = As[r0+8][kk+tig];
                af[mf][2] = As[r0][kk+tig+4]; af[mf][3] = As[r0+8][kk+tig+4];
            }
            #pragma unroll
            for (int nf = 0; nf < 4; nf++) {
                int c0 = nb + nf * 8 + g4;
                bf[nf][0] = Bs[c0][kk+tig]; bf[nf][1] = Bs[c0][kk+tig+4];
            }
            #pragma unroll
            for (int mf = 0; mf < 2; mf++)
                #pragma unroll
                for (int nf = 0; nf < 4; nf++) mma8(acc[mf][nf], af[mf], bf[nf]);
        }
        __syncthreads();
    }
    #pragma unroll
    for (int mf = 0; mf < 2; mf++)
        #pragma unroll
        for (int nf = 0; nf < 4; nf++) {
            int col = n0 + nb + nf * 8 + tig * 2;
            float b0 = bias[col]   + (col   < 2*H_ ? bhh[col]   : 0.f);
            float b1 = bias[col+1] + (col+1 < 2*H_ ? bhh[col+1] : 0.f);
            int r0 = m0 + mb + mf * 16 + g4;
            g_gi[(size_t)r0*G3H+col]       = acc[mf][nf][0] + b0;
            g_gi[(size_t)r0*G3H+col+1]     = acc[mf][nf][1] + b1;
            g_gi[(size_t)(r0+8)*G3H+col]   = acc[mf][nf][2] + b0;
            g_gi[(size_t)(r0+8)*G3H+col+1] = acc[mf][nf][3] + b1;
        }
}

// ---------------------------------------------------------------------------
// Persistent scan, wide-M warp tile (64x48) with 8-way interleaved k-split.
// Grid = 128 CTAs (bt 2 x cg 64), 256 threads / 8 warps.
// Warp w handles kk-group w of every 64-k chunk: dup_A = dup_W = 1.
// Per-step k-split reduction through the (idle) staging buffer.
// ---------------------------------------------------------------------------
#define GRABCASE(S_, MF_, RO_) \
    case S_: { _Pragma("unroll") \
        for (int nf = 0; nf < 6; nf++) { \
            pv[nf*2]   = acc[MF_][nf][RO_*2]; \
            pv[nf*2+1] = acc[MF_][nf][RO_*2+1]; } } break;

__global__ __launch_bounds__(256, 1) void gru_scan(
    const float* __restrict__ Whh, const float* __restrict__ bhh,
    const int* __restrict__ lens, const float* __restrict__ h0,
    float* __restrict__ y_last, float* __restrict__ h_final)
{
    extern __shared__ uint32_t sm[];
    uint32_t* Ws = sm;                       // WS_WORDS, fragment-packed W
    uint32_t* Ab = sm + WS_WORDS;            // 2 x CHUNK_WORDS staging
    float* Sf = reinterpret_cast<float*>(Ab);// reduction scratch (aliases buf0)

    int cta = blockIdx.x;
    int bt = cta & 1, cg = cta >> 1;
    int tid = threadIdx.x, warp = tid >> 5, lane = tid & 31;
    int g4 = lane >> 2, tig = lane & 3;
    int jbase = cg * 16;
    uint32_t ab_u32 = (uint32_t)__cvta_generic_to_shared(Ab);

    // Pack W slice (48 rows x 1024 k) into B-fragment order:
    // word = (nf*128 + kg)*64 + lane*2 + reg,  lane = (j&7)*4 + (k&3), reg=(k>>2)&1
    for (int i = tid; i < 48 * 256; i += 256) {
        int j = i >> 8, c4 = i & 255;
        int q = j >> 4, jl = j & 15;
        int nf = j >> 3, g4r = j & 7;
        float4 v = *reinterpret_cast<const float4*>(
            Whh + (size_t)(q * H_ + jbase + jl) * H_ + c4 * 4);
        int kg = c4 >> 1, reg = c4 & 1;
        uint32_t* d = Ws + ((size_t)nf * 128 + kg) * 64 + g4r * 8 + reg;
        d[0] = f2tf(v.x); d[2] = f2tf(v.y); d[4] = f2tf(v.z); d[6] = f2tf(v.w);
    }

    // Epilogue ownership: thread t -> local row ml = t>>2, cols jl4..jl4+4 per gate
    int ml = tid >> 2;
    int mg = bt * 64 + ml;
    int jl4 = (tid & 3) * 4;
    int jcol = jbase + jl4;
    int len = lens[mg];
    float hreg[4], bn[4];
    #pragma unroll
    for (int e = 0; e < 4; e++) {
        hreg[e] = h0[(size_t)mg * H_ + jcol + e];
        bn[e]   = bhh[2 * H_ + jcol + e];
        g_htf[0][hpack(mg, jcol + e)] = f2tf(hreg[e]);
    }
    __threadfence();
    __syncthreads();
    unsigned phase = 1;
    if (tid == 0) {
        atomicAdd(&g_bar, 1u);
        unsigned v;
        do { asm volatile("ld.global.acquire.gpu.u32 %0, [%1];" : "=r"(v) : "l"(&g_bar) : "memory"); }
        while (v < (unsigned)NCTA * phase);
    }
    __syncthreads();

    for (int t = 0; t < T_; t++) {
        const uint32_t* hin = g_htf[t & 1];
        uint32_t* hout = g_htf[(t & 1) ^ 1];

        // prefetch chunk 0
        #pragma unroll
        for (int it = 0; it < 4; it++)
            cp16cg(ab_u32 + (uint32_t)(it * 1024 + tid * 4) * 4,
                   hin + (size_t)(bt * 4 + it) * RBW + tid * 4);
        asm volatile("cp.async.commit_group;\n" ::: "memory");

        // gi prefetch (hidden behind GEMM)
        float4 gi4[3];
        {
            const float* gp = g_gi + ((size_t)t * B_ + mg) * G3H + jcol;
            #pragma unroll
            for (int q = 0; q < 3; q++)
                gi4[q] = *reinterpret_cast<const float4*>(gp + q * H_);
        }

        float acc[4][6][4];
        #pragma unroll
        for (int mf = 0; mf < 4; mf++)
            #pragma unroll
            for (int nf = 0; nf < 6; nf++)
                #pragma unroll
                for (int k = 0; k < 4; k++) acc[mf][nf][k] = 0.f;

        for (int c = 0; c < 16; c++) {
            asm volatile("cp.async.wait_group 0;\n" ::: "memory");
            __syncthreads();
            if (c + 1 < 16) {
                uint32_t dstb = ab_u32 + (uint32_t)(((c + 1) & 1) * CHUNK_WORDS) * 4;
                #pragma unroll
                for (int it = 0; it < 4; it++)
                    cp16cg(dstb + (uint32_t)(it * 1024 + tid * 4) * 4,
                           hin + (size_t)(bt * 4 + it) * RBW + (c + 1) * 1024 + tid * 4);
                asm volatile("cp.async.commit_group;\n" ::: "memory");
            }

            // this warp's kk-group: kg = c*8 + warp
            uint32_t wf[6][2];
            const uint32_t* Wp = Ws + ((size_t)(c * 8 + warp)) * 64 + lane * 2;
            #pragma unroll
            for (int nf = 0; nf < 6; nf++) {
                uint2 u = *reinterpret_cast<const uint2*>(Wp + (size_t)nf * 8192);
                wf[nf][0] = u.x; wf[nf][1] = u.y;
            }
            const uint32_t* As = Ab + (c & 1) * CHUNK_WORDS + warp * 128 + lane * 4;
            #pragma unroll
            for (int mf = 0; mf < 4; mf++) {
                uint4 af = *reinterpret_cast<const uint4*>(As + mf * 1024);
                #pragma unroll
                for (int nf = 0; nf < 6; nf++)
                    mma8(acc[mf][nf], reinterpret_cast<const uint32_t*>(&af), wf[nf]);
            }
        }

        // k-split reduction: 8 rounds, rotating disjoint 8-row slices, in Sf.
        // Sf layout: [col 0..47][row 0..63], row stride 68 (conflict-free).
        #pragma unroll
        for (int r = 0; r < 8; r++) {
            int s = (warp + r) & 7;
            float pv[12];
            switch (s) {
                GRABCASE(0,0,0) GRABCASE(1,0,1) GRABCASE(2,1,0) GRABCASE(3,1,1)
                GRABCASE(4,2,0) GRABCASE(5,2,1) GRABCASE(6,3,0) GRABCASE(7,3,1)
            }
            int rb = 8 * s + g4;
            if (r == 0) {
                #pragma unroll
                for (int nf = 0; nf < 6; nf++) {
                    Sf[(nf*8 + tig*2    ) * 68 + rb] = pv[nf*2];
                    Sf[(nf*8 + tig*2 + 1) * 68 + rb] = pv[nf*2+1];
                }
            } else {
                #pragma unroll
                for (int nf = 0; nf < 6; nf++) {
                    Sf[(nf*8 + tig*2    ) * 68 + rb] += pv[nf*2];
                    Sf[(nf*8 + tig*2 + 1) * 68 + rb] += pv[nf*2+1];
                }
            }
            __syncthreads();
        }

        // Gate epilogue: thread reads its 12 sums, updates 4 h elements
        float gh[12];
        #pragma unroll
        for (int q = 0; q < 3; q++)
            #pragma unroll
            for (int e = 0; e < 4; e++)
                gh[q*4+e] = Sf[(q*16 + jl4 + e) * 68 + ml];

        bool msk = t < len;
        float yv[4];
        #pragma unroll
        for (int e = 0; e < 4; e++) {
            float gr = reinterpret_cast<const float*>(&gi4[0])[e] + gh[e];
            float gz = reinterpret_cast<const float*>(&gi4[1])[e] + gh[4+e];
            float gn = reinterpret_cast<const float*>(&gi4[2])[e];
            float rg = 1.f / (1.f + __expf(-gr));
            float zg = 1.f / (1.f + __expf(-gz));
            float ng = tanhf(gn + rg * (gh[8+e] + bn[e]));
            float hnew = (1.f - zg) * ng + zg * hreg[e];
            float hv = msk ? hnew : hreg[e];
            hreg[e] = hv;
            yv[e] = msk ? hnew : 0.f;
            hout[hpack(mg, jcol + e)] = f2tf(hv);
        }

        // barrier arrive; overlap y/h_final stores with wait
        __threadfence();
        __syncthreads();
        phase++;
        if (tid == 0) atomicAdd(&g_bar, 1u);

        *reinterpret_cast<float4*>((y_last ? y_last : g_ys) +
            ((size_t)t * B_ + mg) * H_ + jcol) = make_float4(yv[0], yv[1], yv[2], yv[3]);
        if (t == T_ - 1)
            *reinterpret_cast<float4*>(h_final + (size_t)mg * H_ + jcol) =
                make_float4(hreg[0], hreg[1], hreg[2], hreg[3]);

        if (tid == 0) {
            unsigned target = (unsigned)NCTA * phase;
            unsigned v;
            do { asm volatile("ld.global.acquire.gpu.u32 %0, [%1];" : "=r"(v) : "l"(&g_bar) : "memory"); }
            while (v < target);
        }
        __syncthreads();
    }

    // reset barrier for next scan / graph replay
    if (tid == 0) {
        unsigned a = atomicAdd(&g_ack, 1u);
        if (a == (unsigned)(NCTA - 1)) { g_bar = 0u; g_ack = 0u; __threadfence(); }
    }
}

extern "C" void kernel_launch(void* const* d_in, const int* in_sizes, int n_in,
                              void* d_out, int out_size) {
    const float* x         = (const float*)d_in[0];
    const float* hidden    = (const float*)d_in[1];
    const float* w_ih0     = (const float*)d_in[2];
    const float* w_ih_rest = (const float*)d_in[3];
    const float* w_hh      = (const float*)d_in[4];
    const float* b_ih      = (const float*)d_in[5];
    const float* b_hh      = (const float*)d_in[6];
    const int*   lens      = (const int*)d_in[n_in - 1];

    float* out_ys = (float*)d_out;
    float* out_h  = out_ys + (size_t)T_ * B_ * H_;

    cudaFuncSetAttribute(gru_scan, cudaFuncAttributeMaxDynamicSharedMemorySize,
                         SCAN_SMEM_BYTES);

    for (int l = 0; l < L_; l++) {
        int K = (l == 0) ? I_ : H_;
        const float* wih = (l == 0) ? w_ih0 : (w_ih_rest + (size_t)(l - 1) * G3H * H_);
        dim3 grid(G3H / 64, TB / 128);
        gi_gemm<<<grid, 256>>>((l == 0) ? x : nullptr, wih,
                               b_ih + (size_t)l * G3H, b_hh + (size_t)l * G3H, K);
        gru_scan<<<NCTA, 256, SCAN_SMEM_BYTES>>>(
            w_hh + (size_t)l * G3H * H_,
            b_hh + (size_t)l * G3H,
            lens,
            hidden + (size_t)l * B_ * H_,
            (l == L_ - 1) ? out_ys : nullptr,
            out_h + (size_t)l * B_ * H_);
    }
}

// round 14
// speedup vs baseline: 1.4051x; 1.2738x over previous
#include <cuda_runtime.h>
#include <cstdint>

#define T_  256
#define B_  128
#define I_  512
#define H_  1024
#define L_  4
#define G3H 3072
#define TB  (T_ * B_)

#define NCTA 128
#define RBW 16384                 // 16-row block stride in g_htf (words)
#define WS_WORDS (48 * 1024)      // fragment-packed W (words)
#define STG_WORDS 8192            // 8 warps x 2 buffers x 512 words (32KB)
#define SCAN_SMEM_BYTES ((WS_WORDS + STG_WORDS) * 4)   // 229376 <= 232448

// Scratch
__device__ float    g_gi[(size_t)TB * G3H];
__device__ float    g_ys[(size_t)TB * H_];
__device__ uint32_t g_htf[2][B_ * H_];   // h ping-pong, TF32 bits, fragment-packed
__device__ unsigned g_bar, g_ack;

__device__ __forceinline__ uint32_t f2tf(float x) {
    uint32_t r; asm("cvt.rna.tf32.f32 %0, %1;\n" : "=r"(r) : "f"(x)); return r;
}
__device__ __forceinline__ void mma8(float* c, const uint32_t* a, const uint32_t* b) {
    asm volatile("mma.sync.aligned.m16n8k8.row.col.f32.tf32.tf32.f32 "
        "{%0,%1,%2,%3}, {%4,%5,%6,%7}, {%8,%9}, {%0,%1,%2,%3};\n"
        : "+f"(c[0]), "+f"(c[1]), "+f"(c[2]), "+f"(c[3])
        : "r"(a[0]), "r"(a[1]), "r"(a[2]), "r"(a[3]), "r"(b[0]), "r"(b[1]));
}
__device__ __forceinline__ void cp16cg(uint32_t d, const void* s) {
    asm volatile("cp.async.cg.shared.global [%0], [%1], 16;\n" :: "r"(d), "l"(s));
}
// packed address of h element (m, k)  [proven since round 4]
__device__ __forceinline__ int hpack(int m, int k) {
    return (m >> 4) * RBW + (k >> 3) * 128 +
           ((m & 7) * 4 + (k & 3)) * 4 + ((m >> 3) & 1) + 2 * ((k >> 2) & 1);
}

// ---------------- gi = A @ Wih^T + b_ih (+ b_hh folded for r/z gates) -------
__global__ __launch_bounds__(256) void gi_gemm(
    const float* __restrict__ A_ext, const float* __restrict__ W,
    const float* __restrict__ bias, const float* __restrict__ bhh, int K)
{
    __shared__ uint32_t As[128][36];
    __shared__ uint32_t Bs[64][36];
    const float* A = A_ext ? A_ext : g_ys;
    int n0 = blockIdx.x * 64, m0 = blockIdx.y * 128;
    int tid = threadIdx.x, warp = tid >> 5, lane = tid & 31;
    int g4 = lane >> 2, tig = lane & 3;
    int mb = (warp & 3) * 32, nb = (warp >> 2) * 32;
    float acc[2][4][4];
    #pragma unroll
    for (int i = 0; i < 2; i++)
        #pragma unroll
        for (int j = 0; j < 4; j++)
            #pragma unroll
            for (int k = 0; k < 4; k++) acc[i][j][k] = 0.f;
    int arow = tid >> 3, acol = (tid & 7) * 4;
    for (int k0 = 0; k0 < K; k0 += 32) {
        #pragma unroll
        for (int r = 0; r < 4; r++) {
            int row = arow + r * 32;
            float4 v = *reinterpret_cast<const float4*>(A + (size_t)(m0 + row) * K + k0 + acol);
            As[row][acol] = f2tf(v.x); As[row][acol+1] = f2tf(v.y);
            As[row][acol+2] = f2tf(v.z); As[row][acol+3] = f2tf(v.w);
        }
        #pragma unroll
        for (int r = 0; r < 2; r++) {
            int row = arow + r * 32;
            float4 v = *reinterpret_cast<const float4*>(W + (size_t)(n0 + row) * K + k0 + acol);
            Bs[row][acol] = f2tf(v.x); Bs[row][acol+1] = f2tf(v.y);
            Bs[row][acol+2] = f2tf(v.z); Bs[row][acol+3] = f2tf(v.w);
        }
        __syncthreads();
        #pragma unroll
        for (int kk = 0; kk < 32; kk += 8) {
            uint32_t af[2][4], bf[4][2];
            #pragma unroll
            for (int mf = 0; mf < 2; mf++) {
                int r0 = mb + mf * 16 + g4;
                af[mf][0] = As[r0][kk+tig];   af[mf][1] = As[r0+8][kk+tig];
                af[mf][2] = As[r0][kk+tig+4]; af[mf][3] = As[r0+8][kk+tig+4];
            }
            #pragma unroll
            for (int nf = 0; nf < 4; nf++) {
                int c0 = nb + nf * 8 + g4;
                bf[nf][0] = Bs[c0][kk+tig]; bf[nf][1] = Bs[c0][kk+tig+4];
            }
            #pragma unroll
            for (int mf = 0; mf < 2; mf++)
                #pragma unroll
                for (int nf = 0; nf < 4; nf++) mma8(acc[mf][nf], af[mf], bf[nf]);
        }
        __syncthreads();
    }
    #pragma unroll
    for (int mf = 0; mf < 2; mf++)
        #pragma unroll
        for (int nf = 0; nf < 4; nf++) {
            int col = n0 + nb + nf * 8 + tig * 2;
            float b0 = bias[col]   + (col   < 2*H_ ? bhh[col]   : 0.f);
            float b1 = bias[col+1] + (col+1 < 2*H_ ? bhh[col+1] : 0.f);
            int r0 = m0 + mb + mf * 16 + g4;
            g_gi[(size_t)r0*G3H+col]       = acc[mf][nf][0] + b0;
            g_gi[(size_t)r0*G3H+col+1]     = acc[mf][nf][1] + b1;
            g_gi[(size_t)(r0+8)*G3H+col]   = acc[mf][nf][2] + b0;
            g_gi[(size_t)(r0+8)*G3H+col+1] = acc[mf][nf][3] + b1;
        }
}

// ---------------------------------------------------------------------------
// Persistent scan: 64x48 warp tile, 8-way k-split, PER-WARP autonomous
// staging (private double buffer, cp.async committed one chunk ahead,
// wait_group 1) -> zero __syncthreads in the 16-chunk loop.
// ---------------------------------------------------------------------------
#define GRABCASE(S_, MF_, RO_) \
    case S_: { _Pragma("unroll") \
        for (int nf = 0; nf < 6; nf++) { \
            pv[nf*2]   = acc[MF_][nf][RO_*2]; \
            pv[nf*2+1] = acc[MF_][nf][RO_*2+1]; } } break;

__global__ __launch_bounds__(256, 1) void gru_scan(
    const float* __restrict__ Whh, const float* __restrict__ bhh,
    const int* __restrict__ lens, const float* __restrict__ h0,
    float* __restrict__ y_last, float* __restrict__ h_final)
{
    extern __shared__ uint32_t sm[];
    uint32_t* Ws = sm;                        // fragment-packed W
    uint32_t* Ab = sm + WS_WORDS;             // per-warp staging, 8 x 1024 words
    float* Sf = reinterpret_cast<float*>(Ab); // reduction scratch (aliases staging)

    int cta = blockIdx.x;
    int bt = cta & 1, cg = cta >> 1;
    int tid = threadIdx.x, warp = tid >> 5, lane = tid & 31;
    int g4 = lane >> 2, tig = lane & 3;
    int jbase = cg * 16;

    uint32_t* AbW = Ab + warp * 1024;                 // this warp's 2 buffers
    uint32_t abw_u32 = (uint32_t)__cvta_generic_to_shared(AbW);

    // Pack W slice (48 rows x 1024 k) into B-fragment order
    for (int i = tid; i < 48 * 256; i += 256) {
        int j = i >> 8, c4 = i & 255;
        int q = j >> 4, jl = j & 15;
        int nf = j >> 3, g4r = j & 7;
        float4 v = *reinterpret_cast<const float4*>(
            Whh + (size_t)(q * H_ + jbase + jl) * H_ + c4 * 4);
        int kg = c4 >> 1, reg = c4 & 1;
        uint32_t* d = Ws + ((size_t)nf * 128 + kg) * 64 + g4r * 8 + reg;
        d[0] = f2tf(v.x); d[2] = f2tf(v.y); d[4] = f2tf(v.z); d[6] = f2tf(v.w);
    }

    // Epilogue ownership: thread t -> row ml = t>>2, 4 cols per gate
    int ml = tid >> 2;
    int mg = bt * 64 + ml;
    int jl4 = (tid & 3) * 4;
    int jcol = jbase + jl4;
    int len = lens[mg];
    float hreg[4], bn[4];
    #pragma unroll
    for (int e = 0; e < 4; e++) {
        hreg[e] = h0[(size_t)mg * H_ + jcol + e];
        bn[e]   = bhh[2 * H_ + jcol + e];
        g_htf[0][hpack(mg, jcol + e)] = f2tf(hreg[e]);
    }
    __threadfence();
    __syncthreads();
    unsigned phase = 1;
    if (tid == 0) {
        atomicAdd(&g_bar, 1u);
        unsigned v;
        do { asm volatile("ld.global.acquire.gpu.u32 %0, [%1];" : "=r"(v) : "l"(&g_bar) : "memory"); }
        while (v < (unsigned)NCTA * phase);
    }
    __syncthreads();

    for (int t = 0; t < T_; t++) {
        const uint32_t* hin = g_htf[t & 1];
        uint32_t* hout = g_htf[(t & 1) ^ 1];

        // prefetch chunk 0 (per-warp private slice: kk-group `warp` of chunk 0)
        #pragma unroll
        for (int it = 0; it < 4; it++)
            cp16cg(abw_u32 + (uint32_t)(it * 128 + lane * 4) * 4,
                   hin + (size_t)(bt * 4 + it) * RBW + warp * 128 + lane * 4);
        asm volatile("cp.async.commit_group;\n" ::: "memory");

        // gi prefetch (hidden behind GEMM)
        float4 gi4[3];
        {
            const float* gp = g_gi + ((size_t)t * B_ + mg) * G3H + jcol;
            #pragma unroll
            for (int q = 0; q < 3; q++)
                gi4[q] = *reinterpret_cast<const float4*>(gp + q * H_);
        }

        float acc[4][6][4];
        #pragma unroll
        for (int mf = 0; mf < 4; mf++)
            #pragma unroll
            for (int nf = 0; nf < 6; nf++)
                #pragma unroll
                for (int k = 0; k < 4; k++) acc[mf][nf][k] = 0.f;

        for (int c = 0; c < 16; c++) {
            // commit chunk c+1 first, then wait for chunk c (latency hidden)
            if (c + 1 < 16) {
                uint32_t dstb = abw_u32 + (uint32_t)(((c + 1) & 1) * 512) * 4;
                #pragma unroll
                for (int it = 0; it < 4; it++)
                    cp16cg(dstb + (uint32_t)(it * 128 + lane * 4) * 4,
                           hin + (size_t)(bt * 4 + it) * RBW + (c + 1) * 1024
                               + warp * 128 + lane * 4);
                asm volatile("cp.async.commit_group;\n" ::: "memory");
                asm volatile("cp.async.wait_group 1;\n" ::: "memory");
            } else {
                asm volatile("cp.async.wait_group 0;\n" ::: "memory");
            }

            uint32_t wf[6][2];
            const uint32_t* Wp = Ws + ((size_t)(c * 8 + warp)) * 64 + lane * 2;
            #pragma unroll
            for (int nf = 0; nf < 6; nf++) {
                uint2 u = *reinterpret_cast<const uint2*>(Wp + (size_t)nf * 8192);
                wf[nf][0] = u.x; wf[nf][1] = u.y;
            }
            const uint32_t* As = AbW + (c & 1) * 512 + lane * 4;
            #pragma unroll
            for (int mf = 0; mf < 4; mf++) {
                uint4 af = *reinterpret_cast<const uint4*>(As + mf * 128);
                #pragma unroll
                for (int nf = 0; nf < 6; nf++)
                    mma8(acc[mf][nf], reinterpret_cast<const uint32_t*>(&af), wf[nf]);
            }
        }

        // all warps must finish MMAs before Sf (aliases staging) is written
        __syncthreads();

        // k-split reduction: 8 rounds, rotating disjoint 8-row slices
        #pragma unroll
        for (int r = 0; r < 8; r++) {
            int s = (warp + r) & 7;
            float pv[12];
            switch (s) {
                GRABCASE(0,0,0) GRABCASE(1,0,1) GRABCASE(2,1,0) GRABCASE(3,1,1)
                GRABCASE(4,2,0) GRABCASE(5,2,1) GRABCASE(6,3,0) GRABCASE(7,3,1)
            }
            int rb = 8 * s + g4;
            if (r == 0) {
                #pragma unroll
                for (int nf = 0; nf < 6; nf++) {
                    Sf[(nf*8 + tig*2    ) * 68 + rb] = pv[nf*2];
                    Sf[(nf*8 + tig*2 + 1) * 68 + rb] = pv[nf*2+1];
                }
            } else {
                #pragma unroll
                for (int nf = 0; nf < 6; nf++) {
                    Sf[(nf*8 + tig*2    ) * 68 + rb] += pv[nf*2];
                    Sf[(nf*8 + tig*2 + 1) * 68 + rb] += pv[nf*2+1];
                }
            }
            __syncthreads();
        }

        // Gate epilogue
        float gh[12];
        #pragma unroll
        for (int q = 0; q < 3; q++)
            #pragma unroll
            for (int e = 0; e < 4; e++)
                gh[q*4+e] = Sf[(q*16 + jl4 + e) * 68 + ml];

        bool msk = t < len;
        float yv[4];
        #pragma unroll
        for (int e = 0; e < 4; e++) {
            float gr = reinterpret_cast<const float*>(&gi4[0])[e] + gh[e];
            float gz = reinterpret_cast<const float*>(&gi4[1])[e] + gh[4+e];
            float gn = reinterpret_cast<const float*>(&gi4[2])[e];
            float rg = 1.f / (1.f + __expf(-gr));
            float zg = 1.f / (1.f + __expf(-gz));
            float ng = tanhf(gn + rg * (gh[8+e] + bn[e]));
            float hnew = (1.f - zg) * ng + zg * hreg[e];
            float hv = msk ? hnew : hreg[e];
            hreg[e] = hv;
            yv[e] = msk ? hnew : 0.f;
            hout[hpack(mg, jcol + e)] = f2tf(hv);
        }

        // barrier arrive; overlap y/h_final stores with the wait
        __threadfence();
        __syncthreads();
        phase++;
        if (tid == 0) atomicAdd(&g_bar, 1u);

        *reinterpret_cast<float4*>((y_last ? y_last : g_ys) +
            ((size_t)t * B_ + mg) * H_ + jcol) = make_float4(yv[0], yv[1], yv[2], yv[3]);
        if (t == T_ - 1)
            *reinterpret_cast<float4*>(h_final + (size_t)mg * H_ + jcol) =
                make_float4(hreg[0], hreg[1], hreg[2], hreg[3]);

        if (tid == 0) {
            unsigned target = (unsigned)NCTA * phase;
            unsigned v;
            do { asm volatile("ld.global.acquire.gpu.u32 %0, [%1];" : "=r"(v) : "l"(&g_bar) : "memory"); }
            while (v < target);
        }
        __syncthreads();
    }

    // reset barrier for next scan / graph replay
    if (tid == 0) {
        unsigned a = atomicAdd(&g_ack, 1u);
        if (a == (unsigned)(NCTA - 1)) { g_bar = 0u; g_ack = 0u; __threadfence(); }
    }
}

extern "C" void kernel_launch(void* const* d_in, const int* in_sizes, int n_in,
                              void* d_out, int out_size) {
    const float* x         = (const float*)d_in[0];
    const float* hidden    = (const float*)d_in[1];
    const float* w_ih0     = (const float*)d_in[2];
    const float* w_ih_rest = (const float*)d_in[3];
    const float* w_hh      = (const float*)d_in[4];
    const float* b_ih      = (const float*)d_in[5];
    const float* b_hh      = (const float*)d_in[6];
    const int*   lens      = (const int*)d_in[n_in - 1];

    float* out_ys = (float*)d_out;
    float* out_h  = out_ys + (size_t)T_ * B_ * H_;

    cudaFuncSetAttribute(gru_scan, cudaFuncAttributeMaxDynamicSharedMemorySize,
                         SCAN_SMEM_BYTES);

    for (int l = 0; l < L_; l++) {
        int K = (l == 0) ? I_ : H_;
        const float* wih = (l == 0) ? w_ih0 : (w_ih_rest + (size_t)(l - 1) * G3H * H_);
        dim3 grid(G3H / 64, TB / 128);
        gi_gemm<<<grid, 256>>>((l == 0) ? x : nullptr, wih,
                               b_ih + (size_t)l * G3H, b_hh + (size_t)l * G3H, K);
        gru_scan<<<NCTA, 256, SCAN_SMEM_BYTES>>>(
            w_hh + (size_t)l * G3H * H_,
            b_hh + (size_t)l * G3H,
            lens,
            hidden + (size_t)l * B_ * H_,
            (l == L_ - 1) ? out_ys : nullptr,
            out_h + (size_t)l * B_ * H_);
    }
}

// round 15
// speedup vs baseline: 1.4098x; 1.0033x over previous
#include <cuda_runtime.h>
#include <cstdint>

#define T_  256
#define B_  128
#define I_  512
#define H_  1024
#define L_  4
#define G3H 3072
#define TB  (T_ * B_)

#define NCTA 128
#define RBW 16384                 // 16-row block stride in g_htf (words)
#define WS_WORDS (48 * 1024)      // fragment-packed W (words)
#define STG_WORDS 8192            // 8 warps x 2 buffers x 512 words (32KB)
#define SCAN_SMEM_BYTES ((WS_WORDS + STG_WORDS) * 4)   // 229376 <= 232448

// Scratch
__device__ float    g_gi[(size_t)TB * G3H];
__device__ float    g_ys[(size_t)TB * H_];
__device__ uint32_t g_htf[2][B_ * H_];   // h ping-pong, TF32 bits, fragment-packed
__device__ unsigned g_bar2[2];           // per-batch-tile barrier counters
__device__ unsigned g_ack;

__device__ __forceinline__ uint32_t f2tf(float x) {
    uint32_t r; asm("cvt.rna.tf32.f32 %0, %1;\n" : "=r"(r) : "f"(x)); return r;
}
__device__ __forceinline__ void mma8(float* c, const uint32_t* a, const uint32_t* b) {
    asm volatile("mma.sync.aligned.m16n8k8.row.col.f32.tf32.tf32.f32 "
        "{%0,%1,%2,%3}, {%4,%5,%6,%7}, {%8,%9}, {%0,%1,%2,%3};\n"
        : "+f"(c[0]), "+f"(c[1]), "+f"(c[2]), "+f"(c[3])
        : "r"(a[0]), "r"(a[1]), "r"(a[2]), "r"(a[3]), "r"(b[0]), "r"(b[1]));
}
__device__ __forceinline__ void cp16cg(uint32_t d, const void* s) {
    asm volatile("cp.async.cg.shared.global [%0], [%1], 16;\n" :: "r"(d), "l"(s));
}
// packed address of h element (m, k)  [proven since round 4]
__device__ __forceinline__ int hpack(int m, int k) {
    return (m >> 4) * RBW + (k >> 3) * 128 +
           ((m & 7) * 4 + (k & 3)) * 4 + ((m >> 3) & 1) + 2 * ((k >> 2) & 1);
}

// ---------------------------------------------------------------------------
// gi = A @ Wih^T + b_ih (+ b_hh folded for r/z gates)
// Double-buffered: LDG(next) -> MMA(cur) -> cvt+STS.128(next) -> 1 sync.
// Smem stride 44 (STS.128-able, LDS conflict-free: g4*12+tig distinct mod 32).
// ---------------------------------------------------------------------------
#define GST 44
__global__ __launch_bounds__(256, 2) void gi_gemm(
    const float* __restrict__ A_ext, const float* __restrict__ W,
    const float* __restrict__ bias, const float* __restrict__ bhh, int K)
{
    __shared__ __align__(16) uint32_t As[2][128][GST];
    __shared__ __align__(16) uint32_t Bs[2][64][GST];
    const float* A = A_ext ? A_ext : g_ys;
    int n0 = blockIdx.x * 64, m0 = blockIdx.y * 128;
    int tid = threadIdx.x, warp = tid >> 5, lane = tid & 31;
    int g4 = lane >> 2, tig = lane & 3;
    int mb = (warp & 3) * 32, nb = (warp >> 2) * 32;
    float acc[2][4][4];
    #pragma unroll
    for (int i = 0; i < 2; i++)
        #pragma unroll
        for (int j = 0; j < 4; j++)
            #pragma unroll
            for (int k = 0; k < 4; k++) acc[i][j][k] = 0.f;
    int arow = tid >> 3, acol = (tid & 7) * 4;

    int niter = K >> 5;
    float4 pa[4], pb[2];

    // load + stage iter 0
    #pragma unroll
    for (int r = 0; r < 4; r++)
        pa[r] = *reinterpret_cast<const float4*>(A + (size_t)(m0 + arow + r * 32) * K + acol);
    #pragma unroll
    for (int r = 0; r < 2; r++)
        pb[r] = *reinterpret_cast<const float4*>(W + (size_t)(n0 + arow + r * 32) * K + acol);
    #pragma unroll
    for (int r = 0; r < 4; r++)
        *reinterpret_cast<uint4*>(&As[0][arow + r * 32][acol]) =
            make_uint4(f2tf(pa[r].x), f2tf(pa[r].y), f2tf(pa[r].z), f2tf(pa[r].w));
    #pragma unroll
    for (int r = 0; r < 2; r++)
        *reinterpret_cast<uint4*>(&Bs[0][arow + r * 32][acol]) =
            make_uint4(f2tf(pb[r].x), f2tf(pb[r].y), f2tf(pb[r].z), f2tf(pb[r].w));
    __syncthreads();

    for (int it = 0; it < niter; it++) {
        int cur = it & 1;
        // prefetch next iter's tiles into registers (hidden under MMAs)
        if (it + 1 < niter) {
            int k0 = (it + 1) << 5;
            #pragma unroll
            for (int r = 0; r < 4; r++)
                pa[r] = *reinterpret_cast<const float4*>(
                    A + (size_t)(m0 + arow + r * 32) * K + k0 + acol);
            #pragma unroll
            for (int r = 0; r < 2; r++)
                pb[r] = *reinterpret_cast<const float4*>(
                    W + (size_t)(n0 + arow + r * 32) * K + k0 + acol);
        }

        #pragma unroll
        for (int kk = 0; kk < 32; kk += 8) {
            uint32_t af[2][4], bf[4][2];
            #pragma unroll
            for (int mf = 0; mf < 2; mf++) {
                int r0 = mb + mf * 16 + g4;
                af[mf][0] = As[cur][r0][kk+tig];   af[mf][1] = As[cur][r0+8][kk+tig];
                af[mf][2] = As[cur][r0][kk+tig+4]; af[mf][3] = As[cur][r0+8][kk+tig+4];
            }
            #pragma unroll
            for (int nf = 0; nf < 4; nf++) {
                int c0 = nb + nf * 8 + g4;
                bf[nf][0] = Bs[cur][c0][kk+tig]; bf[nf][1] = Bs[cur][c0][kk+tig+4];
            }
            #pragma unroll
            for (int mf = 0; mf < 2; mf++)
                #pragma unroll
                for (int nf = 0; nf < 4; nf++) mma8(acc[mf][nf], af[mf], bf[nf]);
        }

        if (it + 1 < niter) {
            int nxt = cur ^ 1;
            #pragma unroll
            for (int r = 0; r < 4; r++)
                *reinterpret_cast<uint4*>(&As[nxt][arow + r * 32][acol]) =
                    make_uint4(f2tf(pa[r].x), f2tf(pa[r].y), f2tf(pa[r].z), f2tf(pa[r].w));
            #pragma unroll
            for (int r = 0; r < 2; r++)
                *reinterpret_cast<uint4*>(&Bs[nxt][arow + r * 32][acol]) =
                    make_uint4(f2tf(pb[r].x), f2tf(pb[r].y), f2tf(pb[r].z), f2tf(pb[r].w));
            __syncthreads();
        }
    }

    #pragma unroll
    for (int mf = 0; mf < 2; mf++)
        #pragma unroll
        for (int nf = 0; nf < 4; nf++) {
            int col = n0 + nb + nf * 8 + tig * 2;
            float b0 = bias[col]   + (col   < 2*H_ ? bhh[col]   : 0.f);
            float b1 = bias[col+1] + (col+1 < 2*H_ ? bhh[col+1] : 0.f);
            int r0 = m0 + mb + mf * 16 + g4;
            g_gi[(size_t)r0*G3H+col]       = acc[mf][nf][0] + b0;
            g_gi[(size_t)r0*G3H+col+1]     = acc[mf][nf][1] + b1;
            g_gi[(size_t)(r0+8)*G3H+col]   = acc[mf][nf][2] + b0;
            g_gi[(size_t)(r0+8)*G3H+col+1] = acc[mf][nf][3] + b1;
        }
}

// ---------------------------------------------------------------------------
// Persistent scan: 64x48 warp tile, 8-way k-split, per-warp autonomous
// staging. Per-batch-tile 64-CTA barriers; final-step barrier skipped.
// ---------------------------------------------------------------------------
#define GRABCASE(S_, MF_, RO_) \
    case S_: { _Pragma("unroll") \
        for (int nf = 0; nf < 6; nf++) { \
            pv[nf*2]   = acc[MF_][nf][RO_*2]; \
            pv[nf*2+1] = acc[MF_][nf][RO_*2+1]; } } break;

__global__ __launch_bounds__(256, 1) void gru_scan(
    const float* __restrict__ Whh, const float* __restrict__ bhh,
    const int* __restrict__ lens, const float* __restrict__ h0,
    float* __restrict__ y_last, float* __restrict__ h_final)
{
    extern __shared__ uint32_t sm[];
    uint32_t* Ws = sm;                        // fragment-packed W
    uint32_t* Ab = sm + WS_WORDS;             // per-warp staging, 8 x 1024 words
    float* Sf = reinterpret_cast<float*>(Ab); // reduction scratch (aliases staging)

    int cta = blockIdx.x;
    int bt = cta & 1, cg = cta >> 1;
    int tid = threadIdx.x, warp = tid >> 5, lane = tid & 31;
    int g4 = lane >> 2, tig = lane & 3;
    int jbase = cg * 16;
    unsigned* barp = &g_bar2[bt];

    uint32_t* AbW = Ab + warp * 1024;
    uint32_t abw_u32 = (uint32_t)__cvta_generic_to_shared(AbW);

    // Pack W slice (48 rows x 1024 k) into B-fragment order
    for (int i = tid; i < 48 * 256; i += 256) {
        int j = i >> 8, c4 = i & 255;
        int q = j >> 4, jl = j & 15;
        int nf = j >> 3, g4r = j & 7;
        float4 v = *reinterpret_cast<const float4*>(
            Whh + (size_t)(q * H_ + jbase + jl) * H_ + c4 * 4);
        int kg = c4 >> 1, reg = c4 & 1;
        uint32_t* d = Ws + ((size_t)nf * 128 + kg) * 64 + g4r * 8 + reg;
        d[0] = f2tf(v.x); d[2] = f2tf(v.y); d[4] = f2tf(v.z); d[6] = f2tf(v.w);
    }

    // Epilogue ownership: thread t -> row ml = t>>2, 4 cols per gate
    int ml = tid >> 2;
    int mg = bt * 64 + ml;
    int jl4 = (tid & 3) * 4;
    int jcol = jbase + jl4;
    int len = lens[mg];
    float hreg[4], bn[4];
    #pragma unroll
    for (int e = 0; e < 4; e++) {
        hreg[e] = h0[(size_t)mg * H_ + jcol + e];
        bn[e]   = bhh[2 * H_ + jcol + e];
        g_htf[0][hpack(mg, jcol + e)] = f2tf(hreg[e]);
    }
    __threadfence();
    __syncthreads();
    unsigned phase = 1;
    if (tid == 0) {
        atomicAdd(barp, 1u);
        unsigned v;
        do { asm volatile("ld.global.acquire.gpu.u32 %0, [%1];" : "=r"(v) : "l"(barp) : "memory"); }
        while (v < 64u * phase);
    }
    __syncthreads();

    for (int t = 0; t < T_; t++) {
        const uint32_t* hin = g_htf[t & 1];
        uint32_t* hout = g_htf[(t & 1) ^ 1];

        // prefetch chunk 0 (per-warp private kk-slice)
        #pragma unroll
        for (int it = 0; it < 4; it++)
            cp16cg(abw_u32 + (uint32_t)(it * 128 + lane * 4) * 4,
                   hin + (size_t)(bt * 4 + it) * RBW + warp * 128 + lane * 4);
        asm volatile("cp.async.commit_group;\n" ::: "memory");

        // gi prefetch (hidden behind GEMM)
        float4 gi4[3];
        {
            const float* gp = g_gi + ((size_t)t * B_ + mg) * G3H + jcol;
            #pragma unroll
            for (int q = 0; q < 3; q++)
                gi4[q] = *reinterpret_cast<const float4*>(gp + q * H_);
        }

        float acc[4][6][4];
        #pragma unroll
        for (int mf = 0; mf < 4; mf++)
            #pragma unroll
            for (int nf = 0; nf < 6; nf++)
                #pragma unroll
                for (int k = 0; k < 4; k++) acc[mf][nf][k] = 0.f;

        for (int c = 0; c < 16; c++) {
            if (c + 1 < 16) {
                uint32_t dstb = abw_u32 + (uint32_t)(((c + 1) & 1) * 512) * 4;
                #pragma unroll
                for (int it = 0; it < 4; it++)
                    cp16cg(dstb + (uint32_t)(it * 128 + lane * 4) * 4,
                           hin + (size_t)(bt * 4 + it) * RBW + (c + 1) * 1024
                               + warp * 128 + lane * 4);
                asm volatile("cp.async.commit_group;\n" ::: "memory");
                asm volatile("cp.async.wait_group 1;\n" ::: "memory");
            } else {
                asm volatile("cp.async.wait_group 0;\n" ::: "memory");
            }

            uint32_t wf[6][2];
            const uint32_t* Wp = Ws + ((size_t)(c * 8 + warp)) * 64 + lane * 2;
            #pragma unroll
            for (int nf = 0; nf < 6; nf++) {
                uint2 u = *reinterpret_cast<const uint2*>(Wp + (size_t)nf * 8192);
                wf[nf][0] = u.x; wf[nf][1] = u.y;
            }
            const uint32_t* As = AbW + (c & 1) * 512 + lane * 4;
            #pragma unroll
            for (int mf = 0; mf < 4; mf++) {
                uint4 af = *reinterpret_cast<const uint4*>(As + mf * 128);
                #pragma unroll
                for (int nf = 0; nf < 6; nf++)
                    mma8(acc[mf][nf], reinterpret_cast<const uint32_t*>(&af), wf[nf]);
            }
        }

        __syncthreads();   // staging (aliased by Sf) no longer in use

        // k-split reduction: 8 rounds, rotating disjoint 8-row slices
        #pragma unroll
        for (int r = 0; r < 8; r++) {
            int s = (warp + r) & 7;
            float pv[12];
            switch (s) {
                GRABCASE(0,0,0) GRABCASE(1,0,1) GRABCASE(2,1,0) GRABCASE(3,1,1)
                GRABCASE(4,2,0) GRABCASE(5,2,1) GRABCASE(6,3,0) GRABCASE(7,3,1)
            }
            int rb = 8 * s + g4;
            if (r == 0) {
                #pragma unroll
                for (int nf = 0; nf < 6; nf++) {
                    Sf[(nf*8 + tig*2    ) * 68 + rb] = pv[nf*2];
                    Sf[(nf*8 + tig*2 + 1) * 68 + rb] = pv[nf*2+1];
                }
            } else {
                #pragma unroll
                for (int nf = 0; nf < 6; nf++) {
                    Sf[(nf*8 + tig*2    ) * 68 + rb] += pv[nf*2];
                    Sf[(nf*8 + tig*2 + 1) * 68 + rb] += pv[nf*2+1];
                }
            }
            __syncthreads();
        }

        // Gate epilogue
        float gh[12];
        #pragma unroll
        for (int q = 0; q < 3; q++)
            #pragma unroll
            for (int e = 0; e < 4; e++)
                gh[q*4+e] = Sf[(q*16 + jl4 + e) * 68 + ml];

        bool msk = t < len;
        float yv[4];
        #pragma unroll
        for (int e = 0; e < 4; e++) {
            float gr = reinterpret_cast<const float*>(&gi4[0])[e] + gh[e];
            float gz = reinterpret_cast<const float*>(&gi4[1])[e] + gh[4+e];
            float gn = reinterpret_cast<const float*>(&gi4[2])[e];
            float rg = 1.f / (1.f + __expf(-gr));
            float zg = 1.f / (1.f + __expf(-gz));
            float ng = tanhf(gn + rg * (gh[8+e] + bn[e]));
            float hnew = (1.f - zg) * ng + zg * hreg[e];
            float hv = msk ? hnew : hreg[e];
            hreg[e] = hv;
            yv[e] = msk ? hnew : 0.f;
            hout[hpack(mg, jcol + e)] = f2tf(hv);
        }

        if (t < T_ - 1) {
            // barrier arrive; overlap y stores with the wait
            __threadfence();
            __syncthreads();
            phase++;
            if (tid == 0) atomicAdd(barp, 1u);

            *reinterpret_cast<float4*>((y_last ? y_last : g_ys) +
                ((size_t)t * B_ + mg) * H_ + jcol) = make_float4(yv[0], yv[1], yv[2], yv[3]);

            if (tid == 0) {
                unsigned target = 64u * phase;
                unsigned v;
                do { asm volatile("ld.global.acquire.gpu.u32 %0, [%1];" : "=r"(v) : "l"(barp) : "memory"); }
                while (v < target);
            }
            __syncthreads();
        } else {
            // last step: no consumer of h(T) -> no barrier
            *reinterpret_cast<float4*>((y_last ? y_last : g_ys) +
                ((size_t)t * B_ + mg) * H_ + jcol) = make_float4(yv[0], yv[1], yv[2], yv[3]);
            *reinterpret_cast<float4*>(h_final + (size_t)mg * H_ + jcol) =
                make_float4(hreg[0], hreg[1], hreg[2], hreg[3]);
        }
    }

    // reset barriers for next scan / graph replay
    __syncthreads();
    if (tid == 0) {
        __threadfence();
        unsigned a = atomicAdd(&g_ack, 1u);
        if (a == (unsigned)(NCTA - 1)) {
            g_bar2[0] = 0u; g_bar2[1] = 0u; g_ack = 0u;
            __threadfence();
        }
    }
}

extern "C" void kernel_launch(void* const* d_in, const int* in_sizes, int n_in,
                              void* d_out, int out_size) {
    const float* x         = (const float*)d_in[0];
    const float* hidden    = (const float*)d_in[1];
    const float* w_ih0     = (const float*)d_in[2];
    const float* w_ih_rest = (const float*)d_in[3];
    const float* w_hh      = (const float*)d_in[4];
    const float* b_ih      = (const float*)d_in[5];
    const float* b_hh      = (const float*)d_in[6];
    const int*   lens      = (const int*)d_in[n_in - 1];

    float* out_ys = (float*)d_out;
    float* out_h  = out_ys + (size_t)T_ * B_ * H_;

    cudaFuncSetAttribute(gru_scan, cudaFuncAttributeMaxDynamicSharedMemorySize,
                         SCAN_SMEM_BYTES);

    for (int l = 0; l < L_; l++) {
        int K = (l == 0) ? I_ : H_;
        const float* wih = (l == 0) ? w_ih0 : (w_ih_rest + (size_t)(l - 1) * G3H * H_);
        dim3 grid(G3H / 64, TB / 128);
        gi_gemm<<<grid, 256>>>((l == 0) ? x : nullptr, wih,
                               b_ih + (size_t)l * G3H, b_hh + (size_t)l * G3H, K);
        gru_scan<<<NCTA, 256, SCAN_SMEM_BYTES>>>(
            w_hh + (size_t)l * G3H * H_,
            b_hh + (size_t)l * G3H,
            lens,
            hidden + (size_t)l * B_ * H_,
            (l == L_ - 1) ? out_ys : nullptr,
            out_h + (size_t)l * B_ * H_);
    }
}